// round 7
// baseline (speedup 1.0000x reference)
#include <cuda_runtime.h>
#include <cstdint>

#define B_ 2
#define S_ 2048
#define D_ 1024
#define H_ 16
#define DEPTH_ 64
#define SCALE_ 0.125f
#define NEG_ (-1.0e9f)

// Scratch (device globals — no allocations allowed)
__device__ float g_Qh[B_*H_*S_*DEPTH_];
__device__ float g_Kh[B_*H_*S_*DEPTH_];
__device__ float g_Vh[B_*H_*S_*DEPTH_];
__device__ float g_ctx[B_*S_*D_];

__device__ __forceinline__ unsigned f2tf32(float f) {
    unsigned u; asm("cvt.rna.tf32.f32 %0, %1;" : "=r"(u) : "f"(f)); return u;
}

#define MMA_TF32(d, a, b)                                                     \
    asm volatile(                                                             \
        "mma.sync.aligned.m16n8k8.row.col.f32.tf32.tf32.f32 "                 \
        "{%0,%1,%2,%3},{%4,%5,%6,%7},{%8,%9},{%0,%1,%2,%3};"                  \
        : "+f"(d[0]), "+f"(d[1]), "+f"(d[2]), "+f"(d[3])                      \
        : "r"(a[0]), "r"(a[1]), "r"(a[2]), "r"(a[3]), "r"(b[0]), "r"(b[1]))

__device__ __forceinline__ uint32_t smem_u32(const void* p) {
    uint32_t a;
    asm("{ .reg .u64 t; cvta.to.shared.u64 t, %1; cvt.u32.u64 %0, t; }"
        : "=r"(a) : "l"(p));
    return a;
}

#define CP_ASYNC16(dst, src) \
    asm volatile("cp.async.cg.shared.global [%0], [%1], 16;" :: "r"(dst), "l"(src) : "memory")
#define CP_COMMIT() asm volatile("cp.async.commit_group;" ::: "memory")
#define CP_WAIT2()  asm volatile("cp.async.wait_group 2;" ::: "memory")
#define CP_WAIT1()  asm volatile("cp.async.wait_group 1;" ::: "memory")
#define CP_WAIT0()  asm volatile("cp.async.wait_group 0;" ::: "memory")

// ---------------------------------------------------------------------------
// tf32 tensor-core GEMM: C = A[4096,1024] @ W[1024,1024] + bias
// 128x128 CTA tile, BK=16, 3-stage cp.async ring of RAW fp32,
// tf32 conversion at fragment-load time.
// ---------------------------------------------------------------------------
template<bool HEADED, bool ZSEL>
__global__ __launch_bounds__(256, 2)
void gemm_tf32_kernel(const float* __restrict__ A0, const float* __restrict__ W0,
                      const float* __restrict__ bias0, float* __restrict__ C0,
                      const float* A1, const float* W1, const float* bias1, float* C1,
                      const float* A2, const float* W2, const float* bias2, float* C2)
{
    __shared__ float As[3][128][20];
    __shared__ float Bs[3][16][132];

    const float* A = A0; const float* W = W0; const float* bias = bias0; float* C = C0;
    if (ZSEL) {
        if (blockIdx.z == 1) { A = A1; W = W1; bias = bias1; C = C1; }
        else if (blockIdx.z == 2) { A = A2; W = W2; bias = bias2; C = C2; }
    }

    const int t    = threadIdx.x;
    const int m0   = blockIdx.y * 128;
    const int n0   = blockIdx.x * 128;
    const int lane = t & 31, warp = t >> 5;
    const int wm   = warp >> 1, wn = warp & 1;
    const int gid  = lane >> 2, tid4 = lane & 3;

    const int ar = t >> 1,  ac = (t & 1) * 8;
    const int br = t >> 4,  bc = (t & 15) * 8;

    const float* Aptr = A + (size_t)(m0 + ar) * 1024 + ac;
    const float* Wptr = W + (size_t)br * 1024 + n0 + bc;

    uint32_t a_dst[3], b_dst[3];
#pragma unroll
    for (int s = 0; s < 3; s++) {
        a_dst[s] = smem_u32(&As[s][ar][ac]);
        b_dst[s] = smem_u32(&Bs[s][br][bc]);
    }

    float acc[2][8][4];
#pragma unroll
    for (int i = 0; i < 2; i++)
#pragma unroll
        for (int j = 0; j < 8; j++)
#pragma unroll
            for (int c = 0; c < 4; c++) acc[i][j][c] = 0.f;

    // prologue: stage tiles 0..2
#pragma unroll
    for (int s = 0; s < 3; s++) {
        const int ko = s * 16;
        CP_ASYNC16(a_dst[s],      Aptr + ko);
        CP_ASYNC16(a_dst[s] + 16, Aptr + ko + 4);
        CP_ASYNC16(b_dst[s],      Wptr + (size_t)ko * 1024);
        CP_ASYNC16(b_dst[s] + 16, Wptr + (size_t)ko * 1024 + 4);
        CP_COMMIT();
    }

    int cur = 0;
    for (int kt = 0; kt < 64; kt++) {
        if (kt < 61) CP_WAIT2();
        else if (kt == 61) CP_WAIT1();
        else CP_WAIT0();
        __syncthreads();

#pragma unroll
        for (int s = 0; s < 2; s++) {
            unsigned af[2][4], bf[8][2];
#pragma unroll
            for (int i = 0; i < 2; i++) {
                const int r = wm * 32 + i * 16 + gid;
                const int kc = 8 * s + tid4;
                af[i][0] = f2tf32(As[cur][r][kc]);
                af[i][1] = f2tf32(As[cur][r + 8][kc]);
                af[i][2] = f2tf32(As[cur][r][kc + 4]);
                af[i][3] = f2tf32(As[cur][r + 8][kc + 4]);
            }
#pragma unroll
            for (int j = 0; j < 8; j++) {
                const int cn = wn * 64 + j * 8 + gid;
                bf[j][0] = f2tf32(Bs[cur][8 * s + tid4][cn]);
                bf[j][1] = f2tf32(Bs[cur][8 * s + 4 + tid4][cn]);
            }
#pragma unroll
            for (int i = 0; i < 2; i++)
#pragma unroll
                for (int j = 0; j < 8; j++) MMA_TF32(acc[i][j], af[i], bf[j]);
        }
        __syncthreads();

        if (kt + 3 < 64) {
            const int ko = (kt + 3) * 16;
            CP_ASYNC16(a_dst[cur],      Aptr + ko);
            CP_ASYNC16(a_dst[cur] + 16, Aptr + ko + 4);
            CP_ASYNC16(b_dst[cur],      Wptr + (size_t)ko * 1024);
            CP_ASYNC16(b_dst[cur] + 16, Wptr + (size_t)ko * 1024 + 4);
            CP_COMMIT();
        }
        cur = (cur == 2) ? 0 : cur + 1;
    }

#pragma unroll
    for (int i = 0; i < 2; i++) {
#pragma unroll
        for (int j = 0; j < 8; j++) {
            const int n = n0 + wn * 64 + j * 8 + tid4 * 2;
            const float b0 = bias[n], b1 = bias[n + 1];
#pragma unroll
            for (int half = 0; half < 2; half++) {
                const int m = m0 + wm * 32 + i * 16 + gid + half * 8;
                const float v0 = acc[i][j][half * 2 + 0] + b0;
                const float v1 = acc[i][j][half * 2 + 1] + b1;
                if (HEADED) {
                    const int bb = m >> 11, s = m & 2047;
                    const int h = n >> 6, dd = n & 63;
                    float* dst = &C[(((size_t)(bb * H_ + h) << 11) + s) * DEPTH_ + dd];
                    dst[0] = v0; dst[1] = v1;
                } else {
                    C[(size_t)m * 1024 + n]     = v0;
                    C[(size_t)m * 1024 + n + 1] = v1;
                }
            }
        }
    }
}

// ---------------------------------------------------------------------------
// MMA attention: cp.async double-buffered K/V (raw fp32), S^T = K @ Q^T,
// fused in-kernel normalization of the CTA's own attn tile at the end.
// ---------------------------------------------------------------------------
#define KSF(p, r, c) Ks[(p) * 4352 + (r) * 68 + (c)]
#define VSF(p, r, c) Vs[(p) * 4352 + (r) * 68 + (c)]
#define PS(r, c)     Ps[(r) * 68 + (c)]
#define ATTN_SMEM_BYTES ((5 * 64 * 68 + 2 * 64 + 64) * 4)

__global__ __launch_bounds__(256, 2)
void attn_mma_kernel(const float* __restrict__ mask, float* __restrict__ attn)
{
    extern __shared__ char smem_raw[];
    float* Ks = (float*)smem_raw;          // [2][64][68] raw fp32 K [key][d]
    float* Vs = Ks + 2 * 4352;             // [2][64][68] raw fp32 V
    float* Ps = Vs + 2 * 4352;             // [64][68] fp32 P [q][key]
    float* Mt = Ps + 4352;                 // [2][64]
    float* rowsum = Mt + 128;              // [64]

    const int t    = threadIdx.x;
    const int bh   = blockIdx.y;
    const int b    = bh >> 4, h = bh & 15;
    const int q0   = blockIdx.x * 64;
    const int lane = t & 31, warp = t >> 5;
    const int gid  = lane >> 2, t4 = lane & 3;

    const int wmS = warp >> 2, wnS = warp & 3;
    const int wq  = warp >> 2, wd  = warp & 3;

    const float* __restrict__ Qbh = g_Qh + (size_t)bh * S_ * DEPTH_;
    const float* __restrict__ Kbh = g_Kh + (size_t)bh * S_ * DEPTH_;
    const float* __restrict__ Vbh = g_Vh + (size_t)bh * S_ * DEPTH_;

    // per-thread staging geometry: r=0..3, idx=t+256r -> key=idx>>4, d4=(idx&15)*4
    uint32_t kdst[4], vdst[4];
    int goff[4];
#pragma unroll
    for (int r = 0; r < 4; r++) {
        const int idx = t + 256 * r, key = idx >> 4, d4 = (idx & 15) * 4;
        const uint32_t so = (uint32_t)(key * 68 + d4) * 4;
        kdst[r] = smem_u32(Ks) + so;
        vdst[r] = smem_u32(Vs) + so;
        goff[r] = key * DEPTH_ + d4;
    }

    // loop-invariant Q^T B-fragments
    unsigned qb[2][8][2];
#pragma unroll
    for (int j = 0; j < 2; j++) {
        const int qn = q0 + wnS * 16 + j * 8 + gid;
        const float* Qrow = Qbh + (size_t)qn * DEPTH_;
#pragma unroll
        for (int s = 0; s < 8; s++) {
            qb[j][s][0] = f2tf32(Qrow[8 * s + t4]);
            qb[j][s][1] = f2tf32(Qrow[8 * s + t4 + 4]);
        }
    }

    if (t < 64) rowsum[t] = 0.f;

    float Oa[2][2][4];
#pragma unroll
    for (int i = 0; i < 2; i++)
#pragma unroll
        for (int j = 0; j < 2; j++)
#pragma unroll
            for (int c = 0; c < 4; c++) Oa[i][j][c] = 0.f;
    float ps_part[2][2] = {{0.f, 0.f}, {0.f, 0.f}};

    // prologue: async-stage tiles 0 and 1; mask tiles 0,1
#pragma unroll
    for (int r = 0; r < 4; r++) {
        CP_ASYNC16(kdst[r], Kbh + goff[r]);
        CP_ASYNC16(vdst[r], Vbh + goff[r]);
    }
    CP_COMMIT();
#pragma unroll
    for (int r = 0; r < 4; r++) {
        CP_ASYNC16(kdst[r] + 17408, Kbh + 4096 + goff[r]);
        CP_ASYNC16(vdst[r] + 17408, Vbh + 4096 + goff[r]);
    }
    CP_COMMIT();
    if (t < 64) {
        Mt[t]      = mask[b * S_ + t] * NEG_;
        Mt[64 + t] = mask[b * S_ + 64 + t] * NEG_;
    }
    __syncthreads();   // Mt visible

    float mreg = 0.f;
    for (int kt = 0; kt < 32; kt++) {
        const int p = kt & 1;
        const int kb = kt * 64;

        if (t < 64 && kt < 30) mreg = mask[b * S_ + kb + 128 + t] * NEG_;

        if (kt >= 30) CP_WAIT0(); else CP_WAIT1();
        __syncthreads();   // tile kt K/V resident

        // S^T = K @ Q^T (cvt at fragment load)
        float sc[2][2][4];
#pragma unroll
        for (int i = 0; i < 2; i++)
#pragma unroll
            for (int j = 0; j < 2; j++)
#pragma unroll
                for (int c = 0; c < 4; c++) sc[i][j][c] = 0.f;

#pragma unroll
        for (int s = 0; s < 8; s++) {
            unsigned af[2][4];
#pragma unroll
            for (int i = 0; i < 2; i++) {
                const int r = wmS * 32 + i * 16 + gid;
                const int kc = 8 * s + t4;
                af[i][0] = f2tf32(KSF(p, r, kc));
                af[i][1] = f2tf32(KSF(p, r + 8, kc));
                af[i][2] = f2tf32(KSF(p, r, kc + 4));
                af[i][3] = f2tf32(KSF(p, r + 8, kc + 4));
            }
#pragma unroll
            for (int i = 0; i < 2; i++)
#pragma unroll
                for (int j = 0; j < 2; j++) MMA_TF32(sc[i][j], af[i], qb[j][s]);
        }

        // exp + scatter P^T frags into Ps[q][key]
#pragma unroll
        for (int i = 0; i < 2; i++) {
            const int kr = wmS * 32 + i * 16 + gid;
            const float m0 = Mt[p * 64 + kr], m1 = Mt[p * 64 + kr + 8];
#pragma unroll
            for (int j = 0; j < 2; j++) {
                const int qc = wnS * 16 + j * 8 + 2 * t4;
                const float p0 = __expf(sc[i][j][0] * SCALE_ + m0);
                const float p1 = __expf(sc[i][j][1] * SCALE_ + m0);
                const float p2 = __expf(sc[i][j][2] * SCALE_ + m1);
                const float p3 = __expf(sc[i][j][3] * SCALE_ + m1);
                PS(qc, kr)         = p0;
                PS(qc + 1, kr)     = p1;
                PS(qc, kr + 8)     = p2;
                PS(qc + 1, kr + 8) = p3;
                ps_part[j][0] += p0 + p2;
                ps_part[j][1] += p1 + p3;
            }
        }
        __syncthreads();   // syncA: Ps ready; K reads of buf p done

        if (t < 64 && kt < 30) Mt[p * 64 + t] = mreg;  // exp consumer done

        // coalesced store of unnormalized 64x64 P tile
#pragma unroll
        for (int r = 0; r < 4; r++) {
            const int idx = t + 256 * r, ql = idx >> 4, k4 = (idx & 15) * 4;
            const float4 pv = *(const float4*)&PS(ql, k4);
            *(float4*)&attn[((size_t)(bh * S_ + q0 + ql)) * S_ + kb + k4] = pv;
        }

        // O += P @ V (cvt at fragment load for V)
#pragma unroll
        for (int s = 0; s < 8; s++) {
            unsigned af[2][4], bf[2][2];
#pragma unroll
            for (int i = 0; i < 2; i++) {
                const int qr = wq * 32 + i * 16 + gid;
                const int kc = 8 * s + t4;
                af[i][0] = f2tf32(PS(qr, kc));     af[i][1] = f2tf32(PS(qr + 8, kc));
                af[i][2] = f2tf32(PS(qr, kc + 4)); af[i][3] = f2tf32(PS(qr + 8, kc + 4));
            }
#pragma unroll
            for (int j = 0; j < 2; j++) {
                const int dn = wd * 16 + j * 8 + gid;
                bf[j][0] = f2tf32(VSF(p, 8 * s + t4, dn));
                bf[j][1] = f2tf32(VSF(p, 8 * s + 4 + t4, dn));
            }
#pragma unroll
            for (int i = 0; i < 2; i++)
#pragma unroll
                for (int j = 0; j < 2; j++) MMA_TF32(Oa[i][j], af[i], bf[j]);
        }
        __syncthreads();   // syncB: buf p fully consumed

        // async-stage tile kt+2 into buf p
        if (kt < 30) {
            const int go = (kb + 128) * DEPTH_;
            const uint32_t bo = (uint32_t)p * 17408;
#pragma unroll
            for (int r = 0; r < 4; r++) {
                CP_ASYNC16(kdst[r] + bo, Kbh + go + goff[r]);
                CP_ASYNC16(vdst[r] + bo, Vbh + go + goff[r]);
            }
            CP_COMMIT();
        }
    }

    // rowsum reduce -> rinv in smem
#pragma unroll
    for (int j = 0; j < 2; j++)
#pragma unroll
        for (int c = 0; c < 2; c++) {
            float v = ps_part[j][c];
            v += __shfl_xor_sync(0xffffffffu, v, 4);
            v += __shfl_xor_sync(0xffffffffu, v, 8);
            v += __shfl_xor_sync(0xffffffffu, v, 16);
            ps_part[j][c] = v;
        }
    if (gid == 0) {
#pragma unroll
        for (int j = 0; j < 2; j++)
#pragma unroll
            for (int c = 0; c < 2; c++)
                atomicAdd(&rowsum[wnS * 16 + j * 8 + 2 * t4 + c], ps_part[j][c]);
    }
    __syncthreads();
    if (t < 64) rowsum[t] = 1.0f / rowsum[t];
    __syncthreads();

    // normalized context out
#pragma unroll
    for (int i = 0; i < 2; i++) {
        const int qr = wq * 32 + i * 16 + gid;
        const float r0 = rowsum[qr];
        const float r1 = rowsum[qr + 8];
#pragma unroll
        for (int j = 0; j < 2; j++) {
            const int dn = wd * 16 + j * 8 + 2 * t4;
            float* dst0 = &g_ctx[((size_t)(b * S_ + q0 + qr)) * D_ + h * DEPTH_ + dn];
            float* dst1 = &g_ctx[((size_t)(b * S_ + q0 + qr + 8)) * D_ + h * DEPTH_ + dn];
            dst0[0] = Oa[i][j][0] * r0; dst0[1] = Oa[i][j][1] * r0;
            dst1[0] = Oa[i][j][2] * r1; dst1[1] = Oa[i][j][3] * r1;
        }
    }

    // fused normalization of this CTA's own attn rows (q0..q0+63, all 2048)
    // __syncthreads above guarantees intra-CTA visibility of prior stores.
    {
        float* base = attn + ((size_t)bh * S_ + q0) * S_;
        for (int it = 0; it < 128; it++) {
            const int idx = t + 256 * it;          // 0..32767 float4s
            const int row = idx >> 9;              // 512 float4 per row
            const int c4  = idx & 511;
            float4* ptr = (float4*)(base + (size_t)row * S_) + c4;
            float4 v = *ptr;
            const float ri = rowsum[row];
            v.x *= ri; v.y *= ri; v.z *= ri; v.w *= ri;
            *ptr = v;
        }
    }
}

// ---------------------------------------------------------------------------
extern "C" void kernel_launch(void* const* d_in, const int* in_sizes, int n_in,
                              void* d_out, int out_size)
{
    const float* q    = (const float*)d_in[0];
    const float* k    = (const float*)d_in[1];
    const float* v    = (const float*)d_in[2];
    const float* mask = (const float*)d_in[3];
    const float* wq   = (const float*)d_in[4];
    const float* bq   = (const float*)d_in[5];
    const float* wk   = (const float*)d_in[6];
    const float* bk   = (const float*)d_in[7];
    const float* wv   = (const float*)d_in[8];
    const float* bv   = (const float*)d_in[9];
    const float* wo   = (const float*)d_in[10];
    const float* bo   = (const float*)d_in[11];

    float* out  = (float*)d_out;
    float* attn = out + (size_t)B_ * S_ * D_;

    float *pQh, *pKh, *pVh, *pCtx;
    cudaGetSymbolAddress((void**)&pQh,  g_Qh);
    cudaGetSymbolAddress((void**)&pKh,  g_Kh);
    cudaGetSymbolAddress((void**)&pVh,  g_Vh);
    cudaGetSymbolAddress((void**)&pCtx, g_ctx);

    static bool attr_set = false;
    if (!attr_set) {
        cudaFuncSetAttribute(attn_mma_kernel,
                             cudaFuncAttributeMaxDynamicSharedMemorySize,
                             ATTN_SMEM_BYTES);
        attr_set = true;
    }

    gemm_tf32_kernel<true, true><<<dim3(8, 32, 3), 256>>>(
        q, wq, bq, pQh,
        k, wk, bk, pKh,
        v, wv, bv, pVh);

    attn_mma_kernel<<<dim3(S_ / 64, B_ * H_), 256, ATTN_SMEM_BYTES>>>(mask, attn);

    gemm_tf32_kernel<false, false><<<dim3(8, 32, 1), 256>>>(
        pCtx, wo, bo, out,
        nullptr, nullptr, nullptr, nullptr,
        nullptr, nullptr, nullptr, nullptr);
}

// round 8
// speedup vs baseline: 1.1246x; 1.1246x over previous
#include <cuda_runtime.h>
#include <cstdint>

#define B_ 2
#define S_ 2048
#define D_ 1024
#define H_ 16
#define DEPTH_ 64
#define SCALE_ 0.125f
#define NEG_ (-1.0e9f)

// Scratch (device globals — no allocations allowed)
__device__ float g_Qh[B_*H_*S_*DEPTH_];
__device__ float g_Kh[B_*H_*S_*DEPTH_];
__device__ float g_Vh[B_*H_*S_*DEPTH_];
__device__ float g_ctx[B_*S_*D_];
__device__ float g_rinv[B_*H_*S_];

__device__ __forceinline__ unsigned f2tf32(float f) {
    unsigned u; asm("cvt.rna.tf32.f32 %0, %1;" : "=r"(u) : "f"(f)); return u;
}

#define MMA_TF32(d, a, b)                                                     \
    asm volatile(                                                             \
        "mma.sync.aligned.m16n8k8.row.col.f32.tf32.tf32.f32 "                 \
        "{%0,%1,%2,%3},{%4,%5,%6,%7},{%8,%9},{%0,%1,%2,%3};"                  \
        : "+f"(d[0]), "+f"(d[1]), "+f"(d[2]), "+f"(d[3])                      \
        : "r"(a[0]), "r"(a[1]), "r"(a[2]), "r"(a[3]), "r"(b[0]), "r"(b[1]))

__device__ __forceinline__ uint32_t smem_u32(const void* p) {
    uint32_t a;
    asm("{ .reg .u64 t; cvta.to.shared.u64 t, %1; cvt.u32.u64 %0, t; }"
        : "=r"(a) : "l"(p));
    return a;
}

#define CP_ASYNC16(dst, src) \
    asm volatile("cp.async.cg.shared.global [%0], [%1], 16;" :: "r"(dst), "l"(src) : "memory")
#define CP_COMMIT() asm volatile("cp.async.commit_group;" ::: "memory")
#define CP_WAIT2()  asm volatile("cp.async.wait_group 2;" ::: "memory")
#define CP_WAIT1()  asm volatile("cp.async.wait_group 1;" ::: "memory")
#define CP_WAIT0()  asm volatile("cp.async.wait_group 0;" ::: "memory")

// ---------------------------------------------------------------------------
// tf32 tensor-core GEMM: C = A[4096,1024] @ W[1024,1024] + bias
// 128x128 CTA tile, BK=16, 3-stage cp.async ring of RAW fp32,
// tf32 conversion at fragment-load time.
// ---------------------------------------------------------------------------
template<bool HEADED, bool ZSEL>
__global__ __launch_bounds__(256, 2)
void gemm_tf32_kernel(const float* __restrict__ A0, const float* __restrict__ W0,
                      const float* __restrict__ bias0, float* __restrict__ C0,
                      const float* A1, const float* W1, const float* bias1, float* C1,
                      const float* A2, const float* W2, const float* bias2, float* C2)
{
    __shared__ float As[3][128][20];
    __shared__ float Bs[3][16][132];

    const float* A = A0; const float* W = W0; const float* bias = bias0; float* C = C0;
    if (ZSEL) {
        if (blockIdx.z == 1) { A = A1; W = W1; bias = bias1; C = C1; }
        else if (blockIdx.z == 2) { A = A2; W = W2; bias = bias2; C = C2; }
    }

    const int t    = threadIdx.x;
    const int m0   = blockIdx.y * 128;
    const int n0   = blockIdx.x * 128;
    const int lane = t & 31, warp = t >> 5;
    const int wm   = warp >> 1, wn = warp & 1;
    const int gid  = lane >> 2, tid4 = lane & 3;

    const int ar = t >> 1,  ac = (t & 1) * 8;
    const int br = t >> 4,  bc = (t & 15) * 8;

    const float* Aptr = A + (size_t)(m0 + ar) * 1024 + ac;
    const float* Wptr = W + (size_t)br * 1024 + n0 + bc;

    uint32_t a_dst[3], b_dst[3];
#pragma unroll
    for (int s = 0; s < 3; s++) {
        a_dst[s] = smem_u32(&As[s][ar][ac]);
        b_dst[s] = smem_u32(&Bs[s][br][bc]);
    }

    float acc[2][8][4];
#pragma unroll
    for (int i = 0; i < 2; i++)
#pragma unroll
        for (int j = 0; j < 8; j++)
#pragma unroll
            for (int c = 0; c < 4; c++) acc[i][j][c] = 0.f;

#pragma unroll
    for (int s = 0; s < 3; s++) {
        const int ko = s * 16;
        CP_ASYNC16(a_dst[s],      Aptr + ko);
        CP_ASYNC16(a_dst[s] + 16, Aptr + ko + 4);
        CP_ASYNC16(b_dst[s],      Wptr + (size_t)ko * 1024);
        CP_ASYNC16(b_dst[s] + 16, Wptr + (size_t)ko * 1024 + 4);
        CP_COMMIT();
    }

    int cur = 0;
    for (int kt = 0; kt < 64; kt++) {
        if (kt < 61) CP_WAIT2();
        else if (kt == 61) CP_WAIT1();
        else CP_WAIT0();
        __syncthreads();

#pragma unroll
        for (int s = 0; s < 2; s++) {
            unsigned af[2][4], bf[8][2];
#pragma unroll
            for (int i = 0; i < 2; i++) {
                const int r = wm * 32 + i * 16 + gid;
                const int kc = 8 * s + tid4;
                af[i][0] = f2tf32(As[cur][r][kc]);
                af[i][1] = f2tf32(As[cur][r + 8][kc]);
                af[i][2] = f2tf32(As[cur][r][kc + 4]);
                af[i][3] = f2tf32(As[cur][r + 8][kc + 4]);
            }
#pragma unroll
            for (int j = 0; j < 8; j++) {
                const int cn = wn * 64 + j * 8 + gid;
                bf[j][0] = f2tf32(Bs[cur][8 * s + tid4][cn]);
                bf[j][1] = f2tf32(Bs[cur][8 * s + 4 + tid4][cn]);
            }
#pragma unroll
            for (int i = 0; i < 2; i++)
#pragma unroll
                for (int j = 0; j < 8; j++) MMA_TF32(acc[i][j], af[i], bf[j]);
        }
        __syncthreads();

        if (kt + 3 < 64) {
            const int ko = (kt + 3) * 16;
            CP_ASYNC16(a_dst[cur],      Aptr + ko);
            CP_ASYNC16(a_dst[cur] + 16, Aptr + ko + 4);
            CP_ASYNC16(b_dst[cur],      Wptr + (size_t)ko * 1024);
            CP_ASYNC16(b_dst[cur] + 16, Wptr + (size_t)ko * 1024 + 4);
            CP_COMMIT();
        }
        cur = (cur == 2) ? 0 : cur + 1;
    }

#pragma unroll
    for (int i = 0; i < 2; i++) {
#pragma unroll
        for (int j = 0; j < 8; j++) {
            const int n = n0 + wn * 64 + j * 8 + tid4 * 2;
            const float b0 = bias[n], b1 = bias[n + 1];
#pragma unroll
            for (int half = 0; half < 2; half++) {
                const int m = m0 + wm * 32 + i * 16 + gid + half * 8;
                const float v0 = acc[i][j][half * 2 + 0] + b0;
                const float v1 = acc[i][j][half * 2 + 1] + b1;
                if (HEADED) {
                    const int bb = m >> 11, s = m & 2047;
                    const int h = n >> 6, dd = n & 63;
                    float* dst = &C[(((size_t)(bb * H_ + h) << 11) + s) * DEPTH_ + dd];
                    dst[0] = v0; dst[1] = v1;
                } else {
                    C[(size_t)m * 1024 + n]     = v0;
                    C[(size_t)m * 1024 + n + 1] = v1;
                }
            }
        }
    }
}

// ---------------------------------------------------------------------------
// MMA attention: cp.async double-buffered K/V (raw fp32), S^T = K @ Q^T,
// unnormalized P stored; normalization in a separate streaming kernel.
// ---------------------------------------------------------------------------
#define KSF(p, r, c) Ks[(p) * 4352 + (r) * 68 + (c)]
#define VSF(p, r, c) Vs[(p) * 4352 + (r) * 68 + (c)]
#define PS(r, c)     Ps[(r) * 68 + (c)]
#define ATTN_SMEM_BYTES ((5 * 64 * 68 + 2 * 64 + 64) * 4)

__global__ __launch_bounds__(256, 2)
void attn_mma_kernel(const float* __restrict__ mask, float* __restrict__ attn)
{
    extern __shared__ char smem_raw[];
    float* Ks = (float*)smem_raw;          // [2][64][68] raw fp32 K [key][d]
    float* Vs = Ks + 2 * 4352;             // [2][64][68] raw fp32 V
    float* Ps = Vs + 2 * 4352;             // [64][68] fp32 P [q][key]
    float* Mt = Ps + 4352;                 // [2][64]
    float* rowsum = Mt + 128;              // [64]

    const int t    = threadIdx.x;
    const int bh   = blockIdx.y;
    const int b    = bh >> 4, h = bh & 15;
    const int q0   = blockIdx.x * 64;
    const int lane = t & 31, warp = t >> 5;
    const int gid  = lane >> 2, t4 = lane & 3;

    const int wmS = warp >> 2, wnS = warp & 3;
    const int wq  = warp >> 2, wd  = warp & 3;

    const float* __restrict__ Qbh = g_Qh + (size_t)bh * S_ * DEPTH_;
    const float* __restrict__ Kbh = g_Kh + (size_t)bh * S_ * DEPTH_;
    const float* __restrict__ Vbh = g_Vh + (size_t)bh * S_ * DEPTH_;

    uint32_t kdst[4], vdst[4];
    int goff[4];
#pragma unroll
    for (int r = 0; r < 4; r++) {
        const int idx = t + 256 * r, key = idx >> 4, d4 = (idx & 15) * 4;
        const uint32_t so = (uint32_t)(key * 68 + d4) * 4;
        kdst[r] = smem_u32(Ks) + so;
        vdst[r] = smem_u32(Vs) + so;
        goff[r] = key * DEPTH_ + d4;
    }

    unsigned qb[2][8][2];
#pragma unroll
    for (int j = 0; j < 2; j++) {
        const int qn = q0 + wnS * 16 + j * 8 + gid;
        const float* Qrow = Qbh + (size_t)qn * DEPTH_;
#pragma unroll
        for (int s = 0; s < 8; s++) {
            qb[j][s][0] = f2tf32(Qrow[8 * s + t4]);
            qb[j][s][1] = f2tf32(Qrow[8 * s + t4 + 4]);
        }
    }

    if (t < 64) rowsum[t] = 0.f;

    float Oa[2][2][4];
#pragma unroll
    for (int i = 0; i < 2; i++)
#pragma unroll
        for (int j = 0; j < 2; j++)
#pragma unroll
            for (int c = 0; c < 4; c++) Oa[i][j][c] = 0.f;
    float ps_part[2][2] = {{0.f, 0.f}, {0.f, 0.f}};

    // prologue: async-stage tiles 0 and 1; mask tiles 0,1
#pragma unroll
    for (int r = 0; r < 4; r++) {
        CP_ASYNC16(kdst[r], Kbh + goff[r]);
        CP_ASYNC16(vdst[r], Vbh + goff[r]);
    }
    CP_COMMIT();
#pragma unroll
    for (int r = 0; r < 4; r++) {
        CP_ASYNC16(kdst[r] + 17408, Kbh + 4096 + goff[r]);
        CP_ASYNC16(vdst[r] + 17408, Vbh + 4096 + goff[r]);
    }
    CP_COMMIT();
    if (t < 64) {
        Mt[t]      = mask[b * S_ + t] * NEG_;
        Mt[64 + t] = mask[b * S_ + 64 + t] * NEG_;
    }
    __syncthreads();

    float mreg = 0.f;
    for (int kt = 0; kt < 32; kt++) {
        const int p = kt & 1;
        const int kb = kt * 64;

        if (t < 64 && kt < 30) mreg = mask[b * S_ + kb + 128 + t] * NEG_;

        if (kt >= 30) CP_WAIT0(); else CP_WAIT1();
        __syncthreads();

        float sc[2][2][4];
#pragma unroll
        for (int i = 0; i < 2; i++)
#pragma unroll
            for (int j = 0; j < 2; j++)
#pragma unroll
                for (int c = 0; c < 4; c++) sc[i][j][c] = 0.f;

#pragma unroll
        for (int s = 0; s < 8; s++) {
            unsigned af[2][4];
#pragma unroll
            for (int i = 0; i < 2; i++) {
                const int r = wmS * 32 + i * 16 + gid;
                const int kc = 8 * s + t4;
                af[i][0] = f2tf32(KSF(p, r, kc));
                af[i][1] = f2tf32(KSF(p, r + 8, kc));
                af[i][2] = f2tf32(KSF(p, r, kc + 4));
                af[i][3] = f2tf32(KSF(p, r + 8, kc + 4));
            }
#pragma unroll
            for (int i = 0; i < 2; i++)
#pragma unroll
                for (int j = 0; j < 2; j++) MMA_TF32(sc[i][j], af[i], qb[j][s]);
        }

#pragma unroll
        for (int i = 0; i < 2; i++) {
            const int kr = wmS * 32 + i * 16 + gid;
            const float m0 = Mt[p * 64 + kr], m1 = Mt[p * 64 + kr + 8];
#pragma unroll
            for (int j = 0; j < 2; j++) {
                const int qc = wnS * 16 + j * 8 + 2 * t4;
                const float p0 = __expf(sc[i][j][0] * SCALE_ + m0);
                const float p1 = __expf(sc[i][j][1] * SCALE_ + m0);
                const float p2 = __expf(sc[i][j][2] * SCALE_ + m1);
                const float p3 = __expf(sc[i][j][3] * SCALE_ + m1);
                PS(qc, kr)         = p0;
                PS(qc + 1, kr)     = p1;
                PS(qc, kr + 8)     = p2;
                PS(qc + 1, kr + 8) = p3;
                ps_part[j][0] += p0 + p2;
                ps_part[j][1] += p1 + p3;
            }
        }
        __syncthreads();   // syncA: Ps ready; K reads of buf p done

        if (t < 64 && kt < 30) Mt[p * 64 + t] = mreg;

#pragma unroll
        for (int r = 0; r < 4; r++) {
            const int idx = t + 256 * r, ql = idx >> 4, k4 = (idx & 15) * 4;
            const float4 pv = *(const float4*)&PS(ql, k4);
            *(float4*)&attn[((size_t)(bh * S_ + q0 + ql)) * S_ + kb + k4] = pv;
        }

#pragma unroll
        for (int s = 0; s < 8; s++) {
            unsigned af[2][4], bf[2][2];
#pragma unroll
            for (int i = 0; i < 2; i++) {
                const int qr = wq * 32 + i * 16 + gid;
                const int kc = 8 * s + t4;
                af[i][0] = f2tf32(PS(qr, kc));     af[i][1] = f2tf32(PS(qr + 8, kc));
                af[i][2] = f2tf32(PS(qr, kc + 4)); af[i][3] = f2tf32(PS(qr + 8, kc + 4));
            }
#pragma unroll
            for (int j = 0; j < 2; j++) {
                const int dn = wd * 16 + j * 8 + gid;
                bf[j][0] = f2tf32(VSF(p, 8 * s + t4, dn));
                bf[j][1] = f2tf32(VSF(p, 8 * s + 4 + t4, dn));
            }
#pragma unroll
            for (int i = 0; i < 2; i++)
#pragma unroll
                for (int j = 0; j < 2; j++) MMA_TF32(Oa[i][j], af[i], bf[j]);
        }
        __syncthreads();   // syncB: buf p fully consumed

        if (kt < 30) {
            const int go = (kb + 128) * DEPTH_;
            const uint32_t bo = (uint32_t)p * 17408;
#pragma unroll
            for (int r = 0; r < 4; r++) {
                CP_ASYNC16(kdst[r] + bo, Kbh + go + goff[r]);
                CP_ASYNC16(vdst[r] + bo, Vbh + go + goff[r]);
            }
            CP_COMMIT();
        }
    }

    // rowsum reduce
#pragma unroll
    for (int j = 0; j < 2; j++)
#pragma unroll
        for (int c = 0; c < 2; c++) {
            float v = ps_part[j][c];
            v += __shfl_xor_sync(0xffffffffu, v, 4);
            v += __shfl_xor_sync(0xffffffffu, v, 8);
            v += __shfl_xor_sync(0xffffffffu, v, 16);
            ps_part[j][c] = v;
        }
    if (gid == 0) {
#pragma unroll
        for (int j = 0; j < 2; j++)
#pragma unroll
            for (int c = 0; c < 2; c++)
                atomicAdd(&rowsum[wnS * 16 + j * 8 + 2 * t4 + c], ps_part[j][c]);
    }
    __syncthreads();

    if (t < 64) g_rinv[(size_t)bh * S_ + q0 + t] = 1.0f / rowsum[t];

#pragma unroll
    for (int i = 0; i < 2; i++) {
        const int qr = wq * 32 + i * 16 + gid;
        const float r0 = 1.0f / rowsum[qr];
        const float r1 = 1.0f / rowsum[qr + 8];
#pragma unroll
        for (int j = 0; j < 2; j++) {
            const int dn = wd * 16 + j * 8 + 2 * t4;
            float* dst0 = &g_ctx[((size_t)(b * S_ + q0 + qr)) * D_ + h * DEPTH_ + dn];
            float* dst1 = &g_ctx[((size_t)(b * S_ + q0 + qr + 8)) * D_ + h * DEPTH_ + dn];
            dst0[0] = Oa[i][j][0] * r0; dst0[1] = Oa[i][j][1] * r0;
            dst1[0] = Oa[i][j][2] * r1; dst1[1] = Oa[i][j][3] * r1;
        }
    }
}

// ---------------------------------------------------------------------------
// Normalize attn in place (dedicated streaming kernel, full-chip occupancy)
// ---------------------------------------------------------------------------
__global__ __launch_bounds__(256)
void norm_attn_kernel(float* __restrict__ attn)
{
    const size_t i = (size_t)blockIdx.x * 256 + threadIdx.x;
    float4 v = ((float4*)attn)[i];
    const float r = g_rinv[i >> 9];
    v.x *= r; v.y *= r; v.z *= r; v.w *= r;
    ((float4*)attn)[i] = v;
}

// ---------------------------------------------------------------------------
extern "C" void kernel_launch(void* const* d_in, const int* in_sizes, int n_in,
                              void* d_out, int out_size)
{
    const float* q    = (const float*)d_in[0];
    const float* k    = (const float*)d_in[1];
    const float* v    = (const float*)d_in[2];
    const float* mask = (const float*)d_in[3];
    const float* wq   = (const float*)d_in[4];
    const float* bq   = (const float*)d_in[5];
    const float* wk   = (const float*)d_in[6];
    const float* bk   = (const float*)d_in[7];
    const float* wv   = (const float*)d_in[8];
    const float* bv   = (const float*)d_in[9];
    const float* wo   = (const float*)d_in[10];
    const float* bo   = (const float*)d_in[11];

    float* out  = (float*)d_out;
    float* attn = out + (size_t)B_ * S_ * D_;

    float *pQh, *pKh, *pVh, *pCtx;
    cudaGetSymbolAddress((void**)&pQh,  g_Qh);
    cudaGetSymbolAddress((void**)&pKh,  g_Kh);
    cudaGetSymbolAddress((void**)&pVh,  g_Vh);
    cudaGetSymbolAddress((void**)&pCtx, g_ctx);

    static bool attr_set = false;
    if (!attr_set) {
        cudaFuncSetAttribute(attn_mma_kernel,
                             cudaFuncAttributeMaxDynamicSharedMemorySize,
                             ATTN_SMEM_BYTES);
        attr_set = true;
    }

    gemm_tf32_kernel<true, true><<<dim3(8, 32, 3), 256>>>(
        q, wq, bq, pQh,
        k, wk, bk, pKh,
        v, wv, bv, pVh);

    attn_mma_kernel<<<dim3(S_ / 64, B_ * H_), 256, ATTN_SMEM_BYTES>>>(mask, attn);

    norm_attn_kernel<<<(B_ * H_ * (size_t)S_ * S_ / 4) / 256, 256>>>(attn);

    gemm_tf32_kernel<false, false><<<dim3(8, 32, 1), 256>>>(
        pCtx, wo, bo, out,
        nullptr, nullptr, nullptr, nullptr,
        nullptr, nullptr, nullptr, nullptr);
}

// round 9
// speedup vs baseline: 1.1888x; 1.0570x over previous
#include <cuda_runtime.h>
#include <cstdint>

#define B_ 2
#define S_ 2048
#define D_ 1024
#define H_ 16
#define DEPTH_ 64
#define SCALE_ 0.125f
#define NEG_ (-1.0e9f)

// Scratch (device globals — no allocations allowed)
__device__ float g_Qh[B_*H_*S_*DEPTH_];
__device__ float g_Kh[B_*H_*S_*DEPTH_];
__device__ float g_Vh[B_*H_*S_*DEPTH_];
__device__ float g_ctx[B_*S_*D_];
__device__ float g_rinv[B_*H_*S_];

__device__ __forceinline__ unsigned f2tf32(float f) {
    unsigned u; asm("cvt.rna.tf32.f32 %0, %1;" : "=r"(u) : "f"(f)); return u;
}

#define MMA_TF32(d, a, b)                                                     \
    asm volatile(                                                             \
        "mma.sync.aligned.m16n8k8.row.col.f32.tf32.tf32.f32 "                 \
        "{%0,%1,%2,%3},{%4,%5,%6,%7},{%8,%9},{%0,%1,%2,%3};"                  \
        : "+f"(d[0]), "+f"(d[1]), "+f"(d[2]), "+f"(d[3])                      \
        : "r"(a[0]), "r"(a[1]), "r"(a[2]), "r"(a[3]), "r"(b[0]), "r"(b[1]))

__device__ __forceinline__ uint32_t smem_u32(const void* p) {
    uint32_t a;
    asm("{ .reg .u64 t; cvta.to.shared.u64 t, %1; cvt.u32.u64 %0, t; }"
        : "=r"(a) : "l"(p));
    return a;
}

#define CP_ASYNC16(dst, src) \
    asm volatile("cp.async.cg.shared.global [%0], [%1], 16;" :: "r"(dst), "l"(src) : "memory")
#define CP_COMMIT() asm volatile("cp.async.commit_group;" ::: "memory")
#define CP_WAIT1()  asm volatile("cp.async.wait_group 1;" ::: "memory")
#define CP_WAIT0()  asm volatile("cp.async.wait_group 0;" ::: "memory")

// ---------------------------------------------------------------------------
// tf32 tensor-core GEMM: C = A[4096,1024] @ W[1024,1024] + bias
// 128x128 CTA tile, BK=16, 2-stage cp.async staging of RAW fp32,
// tf32 conversion at fragment-load time. (Round-6 proven: 87 us/unit)
// ---------------------------------------------------------------------------
template<bool HEADED, bool ZSEL>
__global__ __launch_bounds__(256, 2)
void gemm_tf32_kernel(const float* __restrict__ A0, const float* __restrict__ W0,
                      const float* __restrict__ bias0, float* __restrict__ C0,
                      const float* A1, const float* W1, const float* bias1, float* C1,
                      const float* A2, const float* W2, const float* bias2, float* C2)
{
    __shared__ float As[2][128][20];
    __shared__ float Bs[2][16][132];

    const float* A = A0; const float* W = W0; const float* bias = bias0; float* C = C0;
    if (ZSEL) {
        if (blockIdx.z == 1) { A = A1; W = W1; bias = bias1; C = C1; }
        else if (blockIdx.z == 2) { A = A2; W = W2; bias = bias2; C = C2; }
    }

    const int t    = threadIdx.x;
    const int m0   = blockIdx.y * 128;
    const int n0   = blockIdx.x * 128;
    const int lane = t & 31, warp = t >> 5;
    const int wm   = warp >> 1, wn = warp & 1;
    const int gid  = lane >> 2, tid4 = lane & 3;

    const int ar = t >> 1,  ac = (t & 1) * 8;
    const int br = t >> 4,  bc = (t & 15) * 8;

    const float* Aptr = A + (size_t)(m0 + ar) * 1024 + ac;
    const float* Wptr = W + (size_t)br * 1024 + n0 + bc;

    const uint32_t a_dst0 = smem_u32(&As[0][ar][ac]);
    const uint32_t a_dst1 = smem_u32(&As[1][ar][ac]);
    const uint32_t b_dst0 = smem_u32(&Bs[0][br][bc]);
    const uint32_t b_dst1 = smem_u32(&Bs[1][br][bc]);

    float acc[2][8][4];
#pragma unroll
    for (int i = 0; i < 2; i++)
#pragma unroll
        for (int j = 0; j < 8; j++)
#pragma unroll
            for (int c = 0; c < 4; c++) acc[i][j][c] = 0.f;

    // prologue: async-stage tiles 0 and 1
    CP_ASYNC16(a_dst0,      Aptr);
    CP_ASYNC16(a_dst0 + 16, Aptr + 4);
    CP_ASYNC16(b_dst0,      Wptr);
    CP_ASYNC16(b_dst0 + 16, Wptr + 4);
    CP_COMMIT();
    CP_ASYNC16(a_dst1,      Aptr + 16);
    CP_ASYNC16(a_dst1 + 16, Aptr + 20);
    CP_ASYNC16(b_dst1,      Wptr + 16384);
    CP_ASYNC16(b_dst1 + 16, Wptr + 16384 + 4);
    CP_COMMIT();

    for (int kt = 0; kt < 64; kt++) {
        const int cur = kt & 1;

        if (kt >= 63) CP_WAIT0(); else CP_WAIT1();
        __syncthreads();

#pragma unroll
        for (int s = 0; s < 2; s++) {
            unsigned af[2][4], bf[8][2];
#pragma unroll
            for (int i = 0; i < 2; i++) {
                const int r = wm * 32 + i * 16 + gid;
                const int kc = 8 * s + tid4;
                af[i][0] = f2tf32(As[cur][r][kc]);
                af[i][1] = f2tf32(As[cur][r + 8][kc]);
                af[i][2] = f2tf32(As[cur][r][kc + 4]);
                af[i][3] = f2tf32(As[cur][r + 8][kc + 4]);
            }
#pragma unroll
            for (int j = 0; j < 8; j++) {
                const int cn = wn * 64 + j * 8 + gid;
                bf[j][0] = f2tf32(Bs[cur][8 * s + tid4][cn]);
                bf[j][1] = f2tf32(Bs[cur][8 * s + 4 + tid4][cn]);
            }
#pragma unroll
            for (int i = 0; i < 2; i++)
#pragma unroll
                for (int j = 0; j < 8; j++) MMA_TF32(acc[i][j], af[i], bf[j]);
        }
        __syncthreads();

        if (kt + 2 < 64) {
            const int ko = (kt + 2) * 16;
            const uint32_t ad = cur ? a_dst1 : a_dst0;
            const uint32_t bd = cur ? b_dst1 : b_dst0;
            CP_ASYNC16(ad,      Aptr + ko);
            CP_ASYNC16(ad + 16, Aptr + ko + 4);
            CP_ASYNC16(bd,      Wptr + (size_t)ko * 1024);
            CP_ASYNC16(bd + 16, Wptr + (size_t)ko * 1024 + 4);
            CP_COMMIT();
        }
    }

#pragma unroll
    for (int i = 0; i < 2; i++) {
#pragma unroll
        for (int j = 0; j < 8; j++) {
            const int n = n0 + wn * 64 + j * 8 + tid4 * 2;
            const float b0 = bias[n], b1 = bias[n + 1];
#pragma unroll
            for (int half = 0; half < 2; half++) {
                const int m = m0 + wm * 32 + i * 16 + gid + half * 8;
                const float v0 = acc[i][j][half * 2 + 0] + b0;
                const float v1 = acc[i][j][half * 2 + 1] + b1;
                if (HEADED) {
                    const int bb = m >> 11, s = m & 2047;
                    const int h = n >> 6, dd = n & 63;
                    float* dst = &C[(((size_t)(bb * H_ + h) << 11) + s) * DEPTH_ + dd];
                    dst[0] = v0; dst[1] = v1;
                } else {
                    C[(size_t)m * 1024 + n]     = v0;
                    C[(size_t)m * 1024 + n + 1] = v1;
                }
            }
        }
    }
}

// ---------------------------------------------------------------------------
// MMA attention (round-4/6 proven version): register-prefetch double-buffered
// K/V, S^T = K @ Q^T, unnormalized P stored, separate norm kernel.
// ---------------------------------------------------------------------------
#define KS(p, r, c) Ks[(p) * 4352 + (r) * 68 + (c)]
#define VS(p, r, c) Vs[(p) * 4352 + (r) * 68 + (c)]
#define PS(r, c)    Ps[(r) * 68 + (c)]
#define ATTN_SMEM_BYTES ((5 * 64 * 68 + 2 * 64 + 64) * 4)

__global__ __launch_bounds__(256, 2)
void attn_mma_kernel(const float* __restrict__ mask, float* __restrict__ attn)
{
    extern __shared__ char smem_raw[];
    unsigned* Ks = (unsigned*)smem_raw;
    unsigned* Vs = Ks + 2 * 4352;
    float*    Ps = (float*)(Vs + 2 * 4352);
    float*    Mt = Ps + 4352;
    float*    rowsum = Mt + 128;

    const int t    = threadIdx.x;
    const int bh   = blockIdx.y;
    const int b    = bh >> 4, h = bh & 15;
    const int q0   = blockIdx.x * 64;
    const int lane = t & 31, warp = t >> 5;
    const int gid  = lane >> 2, t4 = lane & 3;

    const int wmS = warp >> 2, wnS = warp & 3;
    const int wq  = warp >> 2, wd  = warp & 3;

    const float* __restrict__ Qbh = g_Qh + (size_t)bh * S_ * DEPTH_;
    const float* __restrict__ Kbh = g_Kh + (size_t)bh * S_ * DEPTH_;
    const float* __restrict__ Vbh = g_Vh + (size_t)bh * S_ * DEPTH_;

    unsigned qb[2][8][2];
#pragma unroll
    for (int j = 0; j < 2; j++) {
        const int qn = q0 + wnS * 16 + j * 8 + gid;
        const float* Qrow = Qbh + (size_t)qn * DEPTH_;
#pragma unroll
        for (int s = 0; s < 8; s++) {
            qb[j][s][0] = f2tf32(Qrow[8 * s + t4]);
            qb[j][s][1] = f2tf32(Qrow[8 * s + t4 + 4]);
        }
    }

    if (t < 64) rowsum[t] = 0.f;

    float Oa[2][2][4];
#pragma unroll
    for (int i = 0; i < 2; i++)
#pragma unroll
        for (int j = 0; j < 2; j++)
#pragma unroll
            for (int c = 0; c < 4; c++) Oa[i][j][c] = 0.f;
    float ps_part[2][2] = {{0.f, 0.f}, {0.f, 0.f}};

    float4 kreg[4], vreg[4];
    float  mreg = 0.f;
#pragma unroll
    for (int r = 0; r < 4; r++) {
        const int idx = t + 256 * r, key = idx >> 4, d4 = (idx & 15) * 4;
        kreg[r] = *(const float4*)&Kbh[(size_t)key * DEPTH_ + d4];
        vreg[r] = *(const float4*)&Vbh[(size_t)key * DEPTH_ + d4];
    }
    if (t < 64) mreg = mask[b * S_ + t] * NEG_;
#pragma unroll
    for (int r = 0; r < 4; r++) {
        const int idx = t + 256 * r, key = idx >> 4, d4 = (idx & 15) * 4;
        uint4 ku, vu;
        ku.x = f2tf32(kreg[r].x); ku.y = f2tf32(kreg[r].y);
        ku.z = f2tf32(kreg[r].z); ku.w = f2tf32(kreg[r].w);
        vu.x = f2tf32(vreg[r].x); vu.y = f2tf32(vreg[r].y);
        vu.z = f2tf32(vreg[r].z); vu.w = f2tf32(vreg[r].w);
        *(uint4*)&KS(0, key, d4) = ku;
        *(uint4*)&VS(0, key, d4) = vu;
    }
    if (t < 64) Mt[t] = mreg;
    __syncthreads();

    for (int kt = 0; kt < 32; kt++) {
        const int p = kt & 1;
        const int kb = kt * 64;

        if (kt < 31) {
            const int kb2 = kb + 64;
#pragma unroll
            for (int r = 0; r < 4; r++) {
                const int idx = t + 256 * r, key = idx >> 4, d4 = (idx & 15) * 4;
                kreg[r] = *(const float4*)&Kbh[(size_t)(kb2 + key) * DEPTH_ + d4];
                vreg[r] = *(const float4*)&Vbh[(size_t)(kb2 + key) * DEPTH_ + d4];
            }
            if (t < 64) mreg = mask[b * S_ + kb2 + t] * NEG_;
        }

        float sc[2][2][4];
#pragma unroll
        for (int i = 0; i < 2; i++)
#pragma unroll
            for (int j = 0; j < 2; j++)
#pragma unroll
                for (int c = 0; c < 4; c++) sc[i][j][c] = 0.f;

#pragma unroll
        for (int s = 0; s < 8; s++) {
            unsigned af[2][4];
#pragma unroll
            for (int i = 0; i < 2; i++) {
                const int r = wmS * 32 + i * 16 + gid;
                const int kc = 8 * s + t4;
                af[i][0] = KS(p, r, kc);     af[i][1] = KS(p, r + 8, kc);
                af[i][2] = KS(p, r, kc + 4); af[i][3] = KS(p, r + 8, kc + 4);
            }
#pragma unroll
            for (int i = 0; i < 2; i++)
#pragma unroll
                for (int j = 0; j < 2; j++) MMA_TF32(sc[i][j], af[i], qb[j][s]);
        }

#pragma unroll
        for (int i = 0; i < 2; i++) {
            const int kr = wmS * 32 + i * 16 + gid;
            const float m0 = Mt[p * 64 + kr], m1 = Mt[p * 64 + kr + 8];
#pragma unroll
            for (int j = 0; j < 2; j++) {
                const int qc = wnS * 16 + j * 8 + 2 * t4;
                const float p0 = __expf(sc[i][j][0] * SCALE_ + m0);
                const float p1 = __expf(sc[i][j][1] * SCALE_ + m0);
                const float p2 = __expf(sc[i][j][2] * SCALE_ + m1);
                const float p3 = __expf(sc[i][j][3] * SCALE_ + m1);
                PS(qc, kr)         = p0;
                PS(qc + 1, kr)     = p1;
                PS(qc, kr + 8)     = p2;
                PS(qc + 1, kr + 8) = p3;
                ps_part[j][0] += p0 + p2;
                ps_part[j][1] += p1 + p3;
            }
        }
        __syncthreads();

        if (kt < 31) {
#pragma unroll
            for (int r = 0; r < 4; r++) {
                const int idx = t + 256 * r, key = idx >> 4, d4 = (idx & 15) * 4;
                uint4 ku, vu;
                ku.x = f2tf32(kreg[r].x); ku.y = f2tf32(kreg[r].y);
                ku.z = f2tf32(kreg[r].z); ku.w = f2tf32(kreg[r].w);
                vu.x = f2tf32(vreg[r].x); vu.y = f2tf32(vreg[r].y);
                vu.z = f2tf32(vreg[r].z); vu.w = f2tf32(vreg[r].w);
                *(uint4*)&KS(p ^ 1, key, d4) = ku;
                *(uint4*)&VS(p ^ 1, key, d4) = vu;
            }
            if (t < 64) Mt[(p ^ 1) * 64 + t] = mreg;
        }

#pragma unroll
        for (int r = 0; r < 4; r++) {
            const int idx = t + 256 * r, ql = idx >> 4, k4 = (idx & 15) * 4;
            const float4 pv = *(const float4*)&PS(ql, k4);
            *(float4*)&attn[((size_t)(bh * S_ + q0 + ql)) * S_ + kb + k4] = pv;
        }

#pragma unroll
        for (int s = 0; s < 8; s++) {
            unsigned af[2][4], bf[2][2];
#pragma unroll
            for (int i = 0; i < 2; i++) {
                const int qr = wq * 32 + i * 16 + gid;
                const int kc = 8 * s + t4;
                af[i][0] = f2tf32(PS(qr, kc));     af[i][1] = f2tf32(PS(qr + 8, kc));
                af[i][2] = f2tf32(PS(qr, kc + 4)); af[i][3] = f2tf32(PS(qr + 8, kc + 4));
            }
#pragma unroll
            for (int j = 0; j < 2; j++) {
                const int dn = wd * 16 + j * 8 + gid;
                bf[j][0] = VS(p, 8 * s + t4, dn);
                bf[j][1] = VS(p, 8 * s + 4 + t4, dn);
            }
#pragma unroll
            for (int i = 0; i < 2; i++)
#pragma unroll
                for (int j = 0; j < 2; j++) MMA_TF32(Oa[i][j], af[i], bf[j]);
        }
        __syncthreads();
    }

#pragma unroll
    for (int j = 0; j < 2; j++)
#pragma unroll
        for (int c = 0; c < 2; c++) {
            float v = ps_part[j][c];
            v += __shfl_xor_sync(0xffffffffu, v, 4);
            v += __shfl_xor_sync(0xffffffffu, v, 8);
            v += __shfl_xor_sync(0xffffffffu, v, 16);
            ps_part[j][c] = v;
        }
    if (gid == 0) {
#pragma unroll
        for (int j = 0; j < 2; j++)
#pragma unroll
            for (int c = 0; c < 2; c++)
                atomicAdd(&rowsum[wnS * 16 + j * 8 + 2 * t4 + c], ps_part[j][c]);
    }
    __syncthreads();

    if (t < 64) g_rinv[(size_t)bh * S_ + q0 + t] = 1.0f / rowsum[t];

#pragma unroll
    for (int i = 0; i < 2; i++) {
        const int qr = wq * 32 + i * 16 + gid;
        const float r0 = 1.0f / rowsum[qr];
        const float r1 = 1.0f / rowsum[qr + 8];
#pragma unroll
        for (int j = 0; j < 2; j++) {
            const int dn = wd * 16 + j * 8 + 2 * t4;
            float* dst0 = &g_ctx[((size_t)(b * S_ + q0 + qr)) * D_ + h * DEPTH_ + dn];
            float* dst1 = &g_ctx[((size_t)(b * S_ + q0 + qr + 8)) * D_ + h * DEPTH_ + dn];
            dst0[0] = Oa[i][j][0] * r0; dst0[1] = Oa[i][j][1] * r0;
            dst1[0] = Oa[i][j][2] * r1; dst1[1] = Oa[i][j][3] * r1;
        }
    }
}

// ---------------------------------------------------------------------------
__global__ __launch_bounds__(256)
void norm_attn_kernel(float* __restrict__ attn)
{
    const size_t i = (size_t)blockIdx.x * 256 + threadIdx.x;
    float4 v = ((float4*)attn)[i];
    const float r = g_rinv[i >> 9];
    v.x *= r; v.y *= r; v.z *= r; v.w *= r;
    ((float4*)attn)[i] = v;
}

// ---------------------------------------------------------------------------
extern "C" void kernel_launch(void* const* d_in, const int* in_sizes, int n_in,
                              void* d_out, int out_size)
{
    const float* q    = (const float*)d_in[0];
    const float* k    = (const float*)d_in[1];
    const float* v    = (const float*)d_in[2];
    const float* mask = (const float*)d_in[3];
    const float* wq   = (const float*)d_in[4];
    const float* bq   = (const float*)d_in[5];
    const float* wk   = (const float*)d_in[6];
    const float* bk   = (const float*)d_in[7];
    const float* wv   = (const float*)d_in[8];
    const float* bv   = (const float*)d_in[9];
    const float* wo   = (const float*)d_in[10];
    const float* bo   = (const float*)d_in[11];

    float* out  = (float*)d_out;
    float* attn = out + (size_t)B_ * S_ * D_;

    float *pQh, *pKh, *pVh, *pCtx;
    cudaGetSymbolAddress((void**)&pQh,  g_Qh);
    cudaGetSymbolAddress((void**)&pKh,  g_Kh);
    cudaGetSymbolAddress((void**)&pVh,  g_Vh);
    cudaGetSymbolAddress((void**)&pCtx, g_ctx);

    static cudaStream_t s2 = nullptr;
    static cudaEvent_t evA = nullptr, evB = nullptr;
    static bool init_done = false;
    if (!init_done) {
        cudaFuncSetAttribute(attn_mma_kernel,
                             cudaFuncAttributeMaxDynamicSharedMemorySize,
                             ATTN_SMEM_BYTES);
        cudaStreamCreateWithFlags(&s2, cudaStreamNonBlocking);
        cudaEventCreateWithFlags(&evA, cudaEventDisableTiming);
        cudaEventCreateWithFlags(&evB, cudaEventDisableTiming);
        init_done = true;
    }

    gemm_tf32_kernel<true, true><<<dim3(8, 32, 3), 256>>>(
        q, wq, bq, pQh,
        k, wk, bk, pKh,
        v, wv, bv, pVh);

    attn_mma_kernel<<<dim3(S_ / 64, B_ * H_), 256, ATTN_SMEM_BYTES>>>(mask, attn);

    // fork: norm (stream s2, HBM-bound) overlaps out-projection (default, tensor-bound)
    cudaEventRecord(evA, 0);
    cudaStreamWaitEvent(s2, evA, 0);

    norm_attn_kernel<<<(B_ * H_ * (size_t)S_ * S_ / 4) / 256, 256, 0, s2>>>(attn);

    gemm_tf32_kernel<false, false><<<dim3(8, 32, 1), 256>>>(
        pCtx, wo, bo, out,
        nullptr, nullptr, nullptr, nullptr,
        nullptr, nullptr, nullptr, nullptr);

    // join
    cudaEventRecord(evB, s2);
    cudaStreamWaitEvent(0, evB, 0);
}